// round 1
// baseline (speedup 1.0000x reference)
#include <cuda_runtime.h>
#include <cuda_bf16.h>

// Problem constants (fixed by the reference)
#define NN   100000   // nodes
#define HIDD 128      // in = hid = out = 128
#define RR   8        // relations
#define EE   75000    // edges per relation

// Scratch (device globals — no allocation allowed in kernel_launch)
__device__ float g_h  [NN * HIDD];   // relu(x @ W_in + b_in)
__device__ float g_acc[NN * HIDD];   // h @ W_self + b_self  + scattered relation terms
__device__ float g_hr [NN * HIDD];   // h @ W_rel[r] (reused per relation)

// ----------------------------------------------------------------------------
// SGEMM: C[M,128] = op(A[M,128]) @ B[128,128] (+ bias) (+ relu)
// BM=128 tile, 256 threads, 8x8 register tile, K chunked by 16.
// ----------------------------------------------------------------------------
#define BM 128
#define BK 16
#define TM 8
#define TN 8

template<bool RELU_IN, bool RELU_OUT, bool HAS_BIAS>
__global__ __launch_bounds__(256, 2)
void gemm128(const float* __restrict__ A, const float* __restrict__ B,
             const float* __restrict__ bias, float* __restrict__ C, int M)
{
    __shared__ float As[BK][BM + 4];   // transposed A chunk: As[k][m]
    __shared__ float Bs[BK][HIDD];     // Bs[k][n]

    const int tid = threadIdx.x;
    const int ty  = tid >> 4;          // 0..15 -> row group
    const int tx  = tid & 15;          // 0..15 -> col group
    const int m0  = blockIdx.x * BM;

    float acc[TM][TN];
    #pragma unroll
    for (int i = 0; i < TM; i++)
        #pragma unroll
        for (int j = 0; j < TN; j++) acc[i][j] = 0.0f;

    const float4* A4 = reinterpret_cast<const float4*>(A);
    const float4* B4 = reinterpret_cast<const float4*>(B);

    for (int k0 = 0; k0 < HIDD; k0 += BK) {
        // Load A chunk (128 rows x 16 k) transposed into As. 512 float4 total.
        #pragma unroll
        for (int it = 0; it < 2; it++) {
            int idx  = tid + it * 256;     // 0..511
            int row  = idx >> 2;           // 0..127
            int kq   = idx & 3;            // which float4 along k (0..3)
            int grow = m0 + row;
            float4 v = make_float4(0.f, 0.f, 0.f, 0.f);
            if (grow < M) v = A4[grow * (HIDD / 4) + (k0 >> 2) + kq];
            if (RELU_IN) {
                v.x = fmaxf(v.x, 0.f); v.y = fmaxf(v.y, 0.f);
                v.z = fmaxf(v.z, 0.f); v.w = fmaxf(v.w, 0.f);
            }
            As[kq * 4 + 0][row] = v.x;
            As[kq * 4 + 1][row] = v.y;
            As[kq * 4 + 2][row] = v.z;
            As[kq * 4 + 3][row] = v.w;
        }
        // Load B chunk (16 k x 128 n). 512 float4 total.
        #pragma unroll
        for (int it = 0; it < 2; it++) {
            int idx = tid + it * 256;      // 0..511
            int kr  = idx >> 5;            // 0..15
            int n4  = idx & 31;            // 0..31
            float4 v = B4[(k0 + kr) * (HIDD / 4) + n4];
            *reinterpret_cast<float4*>(&Bs[kr][n4 * 4]) = v;
        }
        __syncthreads();

        #pragma unroll
        for (int kk = 0; kk < BK; kk++) {
            float a[TM], b[TN];
            #pragma unroll
            for (int i = 0; i < TM; i += 4)
                *reinterpret_cast<float4*>(&a[i]) =
                    *reinterpret_cast<const float4*>(&As[kk][ty * TM + i]);
            #pragma unroll
            for (int j = 0; j < TN; j += 4)
                *reinterpret_cast<float4*>(&b[j]) =
                    *reinterpret_cast<const float4*>(&Bs[kk][tx * TN + j]);
            #pragma unroll
            for (int i = 0; i < TM; i++)
                #pragma unroll
                for (int j = 0; j < TN; j++)
                    acc[i][j] = fmaf(a[i], b[j], acc[i][j]);
        }
        __syncthreads();
    }

    // Epilogue
    #pragma unroll
    for (int i = 0; i < TM; i++) {
        int grow = m0 + ty * TM + i;
        if (grow < M) {
            #pragma unroll
            for (int j = 0; j < TN; j += 4) {
                int n = tx * TN + j;
                float4 v;
                v.x = acc[i][j + 0];
                v.y = acc[i][j + 1];
                v.z = acc[i][j + 2];
                v.w = acc[i][j + 3];
                if (HAS_BIAS) {
                    v.x += bias[n + 0]; v.y += bias[n + 1];
                    v.z += bias[n + 2]; v.w += bias[n + 3];
                }
                if (RELU_OUT) {
                    v.x = fmaxf(v.x, 0.f); v.y = fmaxf(v.y, 0.f);
                    v.z = fmaxf(v.z, 0.f); v.w = fmaxf(v.w, 0.f);
                }
                *reinterpret_cast<float4*>(&C[grow * HIDD + n]) = v;
            }
        }
    }
}

// ----------------------------------------------------------------------------
// Scatter-add: acc[dst] += w * hr[src]  for each edge. One warp per edge,
// each lane handles 4 floats (128/32). atomicAdd -> RED.F32 (no return).
// ----------------------------------------------------------------------------
__global__ __launch_bounds__(256)
void scatter_add_kernel(const float* __restrict__ hr,
                        const int*   __restrict__ src,
                        const int*   __restrict__ dst,
                        const float* __restrict__ w,
                        float*       __restrict__ acc)
{
    int warp = (blockIdx.x * blockDim.x + threadIdx.x) >> 5;
    int lane = threadIdx.x & 31;
    if (warp >= EE) return;

    int   s  = src[warp];
    int   d  = dst[warp];
    float wt = w[warp];

    float4 v = reinterpret_cast<const float4*>(hr + (size_t)s * HIDD)[lane];
    float* p = acc + (size_t)d * HIDD + lane * 4;
    atomicAdd(p + 0, v.x * wt);
    atomicAdd(p + 1, v.y * wt);
    atomicAdd(p + 2, v.z * wt);
    atomicAdd(p + 3, v.w * wt);
}

// ----------------------------------------------------------------------------
// Launch
// ----------------------------------------------------------------------------
extern "C" void kernel_launch(void* const* d_in, const int* in_sizes, int n_in,
                              void* d_out, int out_size)
{
    const float* x      = (const float*)d_in[0];
    const int*   esrc   = (const int*)  d_in[1];
    const int*   edst   = (const int*)  d_in[2];
    const float* ew     = (const float*)d_in[3];
    const float* W_in   = (const float*)d_in[4];
    const float* b_in   = (const float*)d_in[5];
    const float* W_rel  = (const float*)d_in[6];
    const float* W_self = (const float*)d_in[7];
    const float* b_self = (const float*)d_in[8];
    const float* W_out  = (const float*)d_in[9];
    const float* b_out  = (const float*)d_in[10];
    float* out = (float*)d_out;

    float *h, *acc, *hr;
    cudaGetSymbolAddress((void**)&h,   g_h);
    cudaGetSymbolAddress((void**)&acc, g_acc);
    cudaGetSymbolAddress((void**)&hr,  g_hr);

    const int gemm_grid    = (NN + BM - 1) / BM;      // 782
    const int scatter_grid = (EE * 32 + 255) / 256;   // 9375

    // h = relu(x @ W_in + b_in)
    gemm128<false, true, true><<<gemm_grid, 256>>>(x, W_in, b_in, h, NN);

    // acc = h @ W_self + b_self
    gemm128<false, false, true><<<gemm_grid, 256>>>(h, W_self, b_self, acc, NN);

    // acc += sum_r scatter_dst( w * (h @ W_rel[r]) )
    for (int r = 0; r < RR; r++) {
        gemm128<false, false, false><<<gemm_grid, 256>>>(
            h, W_rel + (size_t)r * HIDD * HIDD, nullptr, hr, NN);
        scatter_add_kernel<<<scatter_grid, 256>>>(
            hr, esrc + (size_t)r * EE, edst + (size_t)r * EE,
            ew + (size_t)r * EE, acc);
    }

    // out = relu(acc) @ W_out + b_out
    gemm128<true, false, true><<<gemm_grid, 256>>>(acc, W_out, b_out, out, NN);
}

// round 6
// speedup vs baseline: 1.5892x; 1.5892x over previous
#include <cuda_runtime.h>
#include <cuda_fp16.h>
#include <cstdint>

// Problem constants (fixed by the reference)
#define NN   100000   // nodes
#define HIDD 128      // in = hid = out = 128
#define RR   8        // relations
#define EE   75000    // edges per relation

#define BK   32       // K chunk resident in SMEM
#define LDS_ 40       // padded SMEM row length (32 + 8) -> conflict-free frags

// ----------------------------------------------------------------------------
// Device-global scratch (no allocation allowed in kernel_launch)
// ----------------------------------------------------------------------------
__device__ float g_h  [NN * HIDD];   // relu(x @ W_in + b_in)
__device__ float g_acc[NN * HIDD];   // h @ W_self + b_self + scattered relation terms
__device__ float g_hr [NN * HIDD];   // h @ W_rel[r] (reused per relation)

// Pre-split, pre-transposed weights: 11 matrices of [N=128][K=128] fp16 (row-major).
// index: 0=W_in, 1=W_self, 2..9=W_rel[r], 10=W_out
__device__ __half g_whi[11 * HIDD * HIDD];
__device__ __half g_wlo[11 * HIDD * HIDD];

// ----------------------------------------------------------------------------
// mma.sync m16n8k16 fp16 (row.col) with fp32 accumulate — baseline PTX, sm_80+.
// ----------------------------------------------------------------------------
__device__ __forceinline__ void mma16816(float* c, const uint32_t* a,
                                         uint32_t b0, uint32_t b1) {
    asm volatile(
        "mma.sync.aligned.m16n8k16.row.col.f32.f16.f16.f32 "
        "{%0,%1,%2,%3}, {%4,%5,%6,%7}, {%8,%9}, {%0,%1,%2,%3};"
        : "+f"(c[0]), "+f"(c[1]), "+f"(c[2]), "+f"(c[3])
        : "r"(a[0]), "r"(a[1]), "r"(a[2]), "r"(a[3]), "r"(b0), "r"(b1));
}

// ----------------------------------------------------------------------------
// Weight pre-split: W[K=128][N=128] f32 row-major -> (hi, lo) fp16, [N][K]
// (transposed, K contiguous). One block per matrix.
// ----------------------------------------------------------------------------
__global__ __launch_bounds__(256)
void split_weights(const float* __restrict__ W_in, const float* __restrict__ W_self,
                   const float* __restrict__ W_rel, const float* __restrict__ W_out,
                   __half* __restrict__ whi, __half* __restrict__ wlo)
{
    int b = blockIdx.x;   // 0..10
    const float* W;
    if (b == 0)       W = W_in;
    else if (b == 1)  W = W_self;
    else if (b <= 9)  W = W_rel + (size_t)(b - 2) * HIDD * HIDD;
    else              W = W_out;

    __half* oh = whi + (size_t)b * HIDD * HIDD;
    __half* ol = wlo + (size_t)b * HIDD * HIDD;

    for (int idx = threadIdx.x; idx < HIDD * HIDD; idx += 256) {
        int n = idx >> 7;        // output row (N)
        int k = idx & 127;       // output col (K)
        float v = W[k * HIDD + n];
        __half hi = __float2half_rn(v);
        float res = v - __half2float(hi);
        oh[idx] = hi;
        ol[idx] = __float2half_rn(res);
    }
}

// ----------------------------------------------------------------------------
// HMMA GEMM: C[M,128] = op(A[M,128]) @ Wt^T (+bias)(+relu), fp16 hi/lo split
// (3 MMA passes: hi*hi + hi*lo + lo*hi; lo*lo dropped ~2^-22).
// CTA: 128x128 tile. K streamed in 4 chunks of 32 through 40 KB static SMEM.
// 8 warps = 4(m) x 2(n); warp tile 32x64 -> 2 m16 x 8 n8 mma tiles.
// ----------------------------------------------------------------------------
template<bool RELU_IN, bool RELU_OUT, bool HAS_BIAS>
__global__ __launch_bounds__(256)
void gemm_mma(const float* __restrict__ A,
              const __half* __restrict__ Bhi,
              const __half* __restrict__ Blo,
              const float* __restrict__ bias,
              float* __restrict__ C, int M)
{
    __shared__ __half smAh[128 * LDS_];
    __shared__ __half smAl[128 * LDS_];
    __shared__ __half smBh[128 * LDS_];
    __shared__ __half smBl[128 * LDS_];

    const int tid  = threadIdx.x;
    const int lane = tid & 31;
    const int wid  = tid >> 5;
    const int m0   = blockIdx.x * 128;

    const int g  = lane >> 2;         // 0..7
    const int ct = lane & 3;          // 0..3
    const int wm = (wid >> 1) * 32;   // warp m offset (0,32,64,96)
    const int wn = (wid & 1) * 64;    // warp n offset (0,64)

    float c[2][8][4];
    #pragma unroll
    for (int mi = 0; mi < 2; mi++)
        #pragma unroll
        for (int ni = 0; ni < 8; ni++)
            #pragma unroll
            for (int j = 0; j < 4; j++) c[mi][ni][j] = 0.f;

    const float4* A4 = reinterpret_cast<const float4*>(A);

    for (int kc = 0; kc < HIDD / BK; kc++) {       // 4 chunks
        const int kbase = kc * BK;

        // ---- Load A chunk: f32 -> (hi, lo) fp16, padded SMEM ----
        #pragma unroll
        for (int it = 0; it < 4; it++) {
            int idx = tid + it * 256;      // 0..1023 float4-groups (128 rows x 8)
            int m   = idx >> 3;            // row 0..127
            int kg  = idx & 7;             // float4 index within chunk
            int grow = m0 + m;
            float4 v = make_float4(0.f, 0.f, 0.f, 0.f);
            if (grow < M) v = A4[(size_t)grow * 32 + (kbase >> 2) + kg];
            if (RELU_IN) {
                v.x = fmaxf(v.x, 0.f); v.y = fmaxf(v.y, 0.f);
                v.z = fmaxf(v.z, 0.f); v.w = fmaxf(v.w, 0.f);
            }
            __half hx = __float2half_rn(v.x);
            __half hy = __float2half_rn(v.y);
            __half hz = __float2half_rn(v.z);
            __half hw = __float2half_rn(v.w);
            __half2 h01; h01.x = hx; h01.y = hy;
            __half2 h23; h23.x = hz; h23.y = hw;
            __half2 l01; l01.x = __float2half_rn(v.x - __half2float(hx));
                         l01.y = __float2half_rn(v.y - __half2float(hy));
            __half2 l23; l23.x = __float2half_rn(v.z - __half2float(hz));
                         l23.y = __float2half_rn(v.w - __half2float(hw));

            int off = m * LDS_ + kg * 4;
            uint2 hv, lv;
            hv.x = *reinterpret_cast<uint32_t*>(&h01);
            hv.y = *reinterpret_cast<uint32_t*>(&h23);
            lv.x = *reinterpret_cast<uint32_t*>(&l01);
            lv.y = *reinterpret_cast<uint32_t*>(&l23);
            *reinterpret_cast<uint2*>(smAh + off) = hv;
            *reinterpret_cast<uint2*>(smAl + off) = lv;
        }

        // ---- Load B chunk ([N][K] fp16 row-major) ----
        {
            const uint4* Bh4 = reinterpret_cast<const uint4*>(Bhi);
            const uint4* Bl4 = reinterpret_cast<const uint4*>(Blo);
            #pragma unroll
            for (int it = 0; it < 2; it++) {
                int idx = tid + it * 256;   // 0..511 16B-chunks (128 rows x 4)
                int n   = idx >> 2;         // row 0..127
                int kg  = idx & 3;          // 8-fp16 chunk within BK
                int gidx = (n * HIDD + kbase) / 8 + kg;
                uint4 vh = Bh4[gidx];
                uint4 vl = Bl4[gidx];
                int off = n * LDS_ + kg * 8;
                *reinterpret_cast<uint4*>(smBh + off) = vh;
                *reinterpret_cast<uint4*>(smBl + off) = vl;
            }
        }

        __syncthreads();

        // ---- 2 k16 steps per chunk ----
        #pragma unroll
        for (int ks = 0; ks < 2; ks++) {
            const int k0 = ks * 16;

            uint32_t ah[2][4], al[2][4];
            #pragma unroll
            for (int mi = 0; mi < 2; mi++) {
                int r    = wm + mi * 16 + g;
                int base = r * LDS_ + k0 + ct * 2;
                ah[mi][0] = *reinterpret_cast<const uint32_t*>(smAh + base);
                ah[mi][1] = *reinterpret_cast<const uint32_t*>(smAh + base + 8 * LDS_);
                ah[mi][2] = *reinterpret_cast<const uint32_t*>(smAh + base + 8);
                ah[mi][3] = *reinterpret_cast<const uint32_t*>(smAh + base + 8 * LDS_ + 8);
                al[mi][0] = *reinterpret_cast<const uint32_t*>(smAl + base);
                al[mi][1] = *reinterpret_cast<const uint32_t*>(smAl + base + 8 * LDS_);
                al[mi][2] = *reinterpret_cast<const uint32_t*>(smAl + base + 8);
                al[mi][3] = *reinterpret_cast<const uint32_t*>(smAl + base + 8 * LDS_ + 8);
            }

            #pragma unroll
            for (int ni = 0; ni < 8; ni++) {
                int n  = wn + ni * 8 + g;
                int bb = n * LDS_ + k0 + ct * 2;
                uint32_t bh0 = *reinterpret_cast<const uint32_t*>(smBh + bb);
                uint32_t bh1 = *reinterpret_cast<const uint32_t*>(smBh + bb + 8);
                uint32_t bl0 = *reinterpret_cast<const uint32_t*>(smBl + bb);
                uint32_t bl1 = *reinterpret_cast<const uint32_t*>(smBl + bb + 8);
                #pragma unroll
                for (int mi = 0; mi < 2; mi++) {
                    mma16816(c[mi][ni], ah[mi], bh0, bh1);   // hi * hi
                    mma16816(c[mi][ni], ah[mi], bl0, bl1);   // hi * lo
                    mma16816(c[mi][ni], al[mi], bh0, bh1);   // lo * hi
                }
            }
        }

        __syncthreads();
    }

    // ---- Epilogue: bias / relu, store f32 ----
    #pragma unroll
    for (int mi = 0; mi < 2; mi++) {
        int row0 = m0 + wm + mi * 16 + g;
        #pragma unroll
        for (int ni = 0; ni < 8; ni++) {
            int col = wn + ni * 8 + ct * 2;
            float b0 = 0.f, b1 = 0.f;
            if (HAS_BIAS) { b0 = bias[col]; b1 = bias[col + 1]; }
            float v0 = c[mi][ni][0] + b0, v1 = c[mi][ni][1] + b1;
            float v2 = c[mi][ni][2] + b0, v3 = c[mi][ni][3] + b1;
            if (RELU_OUT) {
                v0 = fmaxf(v0, 0.f); v1 = fmaxf(v1, 0.f);
                v2 = fmaxf(v2, 0.f); v3 = fmaxf(v3, 0.f);
            }
            if (row0 < M) {
                float2 s; s.x = v0; s.y = v1;
                *reinterpret_cast<float2*>(&C[(size_t)row0 * HIDD + col]) = s;
            }
            if (row0 + 8 < M) {
                float2 s; s.x = v2; s.y = v3;
                *reinterpret_cast<float2*>(&C[(size_t)(row0 + 8) * HIDD + col]) = s;
            }
        }
    }
}

// ----------------------------------------------------------------------------
// Scatter-add: acc[dst] += w * hr[src]. One warp per edge; one vector
// atomicAdd(float4) per lane (RED.128).
// ----------------------------------------------------------------------------
__global__ __launch_bounds__(256)
void scatter_add_kernel(const float* __restrict__ hr,
                        const int*   __restrict__ src,
                        const int*   __restrict__ dst,
                        const float* __restrict__ w,
                        float*       __restrict__ acc)
{
    int warp = (blockIdx.x * blockDim.x + threadIdx.x) >> 5;
    int lane = threadIdx.x & 31;
    if (warp >= EE) return;

    int   s  = src[warp];
    int   d  = dst[warp];
    float wt = w[warp];

    float4 v = reinterpret_cast<const float4*>(hr + (size_t)s * HIDD)[lane];
    v.x *= wt; v.y *= wt; v.z *= wt; v.w *= wt;
    atomicAdd(reinterpret_cast<float4*>(acc + (size_t)d * HIDD + lane * 4), v);
}

// ----------------------------------------------------------------------------
// Launch
// ----------------------------------------------------------------------------
extern "C" void kernel_launch(void* const* d_in, const int* in_sizes, int n_in,
                              void* d_out, int out_size)
{
    const float* x      = (const float*)d_in[0];
    const int*   esrc   = (const int*)  d_in[1];
    const int*   edst   = (const int*)  d_in[2];
    const float* ew     = (const float*)d_in[3];
    const float* W_in   = (const float*)d_in[4];
    const float* b_in   = (const float*)d_in[5];
    const float* W_rel  = (const float*)d_in[6];
    const float* W_self = (const float*)d_in[7];
    const float* b_self = (const float*)d_in[8];
    const float* W_out  = (const float*)d_in[9];
    const float* b_out  = (const float*)d_in[10];
    float* out = (float*)d_out;

    float *h, *acc, *hr;
    __half *whi, *wlo;
    cudaGetSymbolAddress((void**)&h,   g_h);
    cudaGetSymbolAddress((void**)&acc, g_acc);
    cudaGetSymbolAddress((void**)&hr,  g_hr);
    cudaGetSymbolAddress((void**)&whi, g_whi);
    cudaGetSymbolAddress((void**)&wlo, g_wlo);

    const int gemm_grid    = (NN + 127) / 128;        // 782
    const int scatter_grid = (EE * 32 + 255) / 256;   // 9375
    const int MSZ = HIDD * HIDD;

    // Pre-split + transpose all weights to fp16 hi/lo, [N][K]
    split_weights<<<11, 256>>>(W_in, W_self, W_rel, W_out, whi, wlo);

    // h = relu(x @ W_in + b_in)
    gemm_mma<false, true, true><<<gemm_grid, 256>>>(
        x, whi + 0 * MSZ, wlo + 0 * MSZ, b_in, h, NN);

    // acc = h @ W_self + b_self
    gemm_mma<false, false, true><<<gemm_grid, 256>>>(
        h, whi + 1 * MSZ, wlo + 1 * MSZ, b_self, acc, NN);

    // acc += sum_r scatter_dst( w * (h @ W_rel[r]) )
    for (int r = 0; r < RR; r++) {
        gemm_mma<false, false, false><<<gemm_grid, 256>>>(
            h, whi + (2 + r) * MSZ, wlo + (2 + r) * MSZ, nullptr, hr, NN);
        scatter_add_kernel<<<scatter_grid, 256>>>(
            hr, esrc + (size_t)r * EE, edst + (size_t)r * EE,
            ew + (size_t)r * EE, acc);
    }

    // out = relu(acc) @ W_out + b_out
    gemm_mma<true, false, true><<<gemm_grid, 256>>>(
        acc, whi + 10 * MSZ, wlo + 10 * MSZ, b_out, out, NN);
}